// round 16
// baseline (speedup 1.0000x reference)
#include <cuda_runtime.h>

#define Hdim 1024
#define Wdim 1024
#define HWdim (Hdim * Wdim)
#define TSH 32
#define TSW 32
#define NT 128

// smem float offsets (OFF_W/OFF_M 16B-aligned for LDS.128)
#define OFF_X   0            // [3][38][38]
#define OFF_C4  4332         // [36][36]
#define OFF_C5  5628         // [34][34]
#define OFF_W   6784         // 12 groups x 16 floats (9 used, padded)
#define OFF_B   6976         // [3]
#define OFF_M   6980         // [12], 16B aligned
#define OFF_B2  6992         // [2]
#define SMEM_FLOATS 6994
#define SMEM_BYTES (SMEM_FLOATS * 4)

__device__ float g_M[12];
__device__ float g_B[2];

__global__ void fold_mlp_kernel(const float* __restrict__ lw1,
                                const float* __restrict__ lb1,
                                const float* __restrict__ lw2,
                                const float* __restrict__ lb2) {
    int t = threadIdx.x;
    if (t < 12) {
        int o = t / 6, c = t % 6;
        float acc = 0.0f;
        #pragma unroll 8
        for (int k = 0; k < 128; k++)
            acc += lw2[o * 128 + k] * lw1[k * 6 + c];
        g_M[t] = acc;
    } else if (t < 14) {
        int o = t - 12;
        float acc = lb2[o];
        #pragma unroll 8
        for (int k = 0; k < 128; k++)
            acc += lw2[o * 128 + k] * lb1[k];
        g_B[o] = acc;
    }
}

__device__ __forceinline__ float sigmoidf_(float y) {
    return __fdividef(1.0f, 1.0f + __expf(-y));
}

// 2x2-output conv accumulate, window starts at P (8B-aligned).
// WSM: 16B-aligned 9-weight group -> 2x LDS.128 + 1x LDS.32 (broadcast).
#define ACC2X2_EVEN(P, S, WSM) do {                                          \
    float4 tA = *(const float4*)(WSM);                                       \
    float4 tB = *(const float4*)((WSM) + 4);                                 \
    float  w8 = (WSM)[8];                                                    \
    _Pragma("unroll")                                                        \
    for (int rr = 0; rr < 4; rr++) {                                         \
        float2 A = *(const float2*)((P) + rr * (S));                         \
        float2 B = *(const float2*)((P) + rr * (S) + 2);                     \
        float w0, w1, w2;                                                    \
        if (rr <= 2) {                                                       \
            w0 = rr == 0 ? tA.x : (rr == 1 ? tA.w : tB.z);                   \
            w1 = rr == 0 ? tA.y : (rr == 1 ? tB.x : tB.w);                   \
            w2 = rr == 0 ? tA.z : (rr == 1 ? tB.y : w8);                     \
            a00 += w0*A.x + w1*A.y + w2*B.x;                                 \
            a01 += w0*A.y + w1*B.x + w2*B.y;                                 \
        }                                                                    \
        if (rr >= 1) {                                                       \
            w0 = rr == 1 ? tA.x : (rr == 2 ? tA.w : tB.z);                   \
            w1 = rr == 1 ? tA.y : (rr == 2 ? tB.x : tB.w);                   \
            w2 = rr == 1 ? tA.z : (rr == 2 ? tB.y : w8);                     \
            a10 += w0*A.x + w1*A.y + w2*B.x;                                 \
            a11 += w0*A.y + w1*B.x + w2*B.y;                                 \
        }                                                                    \
    }                                                                        \
} while (0)

// Window logically starts at P+1 (P 8B-aligned): 3x LDS.64 per row.
#define ACC2X2_ODD(P, S, WSM) do {                                           \
    float4 tA = *(const float4*)(WSM);                                       \
    float4 tB = *(const float4*)((WSM) + 4);                                 \
    float  w8 = (WSM)[8];                                                    \
    _Pragma("unroll")                                                        \
    for (int rr = 0; rr < 4; rr++) {                                         \
        float2 A = *(const float2*)((P) + rr * (S));                         \
        float2 B = *(const float2*)((P) + rr * (S) + 2);                     \
        float2 C = *(const float2*)((P) + rr * (S) + 4);                     \
        float w0, w1, w2;                                                    \
        if (rr <= 2) {                                                       \
            w0 = rr == 0 ? tA.x : (rr == 1 ? tA.w : tB.z);                   \
            w1 = rr == 0 ? tA.y : (rr == 1 ? tB.x : tB.w);                   \
            w2 = rr == 0 ? tA.z : (rr == 1 ? tB.y : w8);                     \
            a00 += w0*A.y + w1*B.x + w2*B.y;                                 \
            a01 += w0*B.x + w1*B.y + w2*C.x;                                 \
        }                                                                    \
        if (rr >= 1) {                                                       \
            w0 = rr == 1 ? tA.x : (rr == 2 ? tA.w : tB.z);                   \
            w1 = rr == 1 ? tA.y : (rr == 2 ? tB.x : tB.w);                   \
            w2 = rr == 1 ? tA.z : (rr == 2 ? tB.y : w8);                     \
            a10 += w0*A.y + w1*B.x + w2*B.y;                                 \
            a11 += w0*B.x + w1*B.y + w2*C.x;                                 \
        }                                                                    \
    }                                                                        \
} while (0)

template <bool INTERIOR>
__device__ __forceinline__ void encoder_pass(
    float* __restrict__ sm, int tid, int h0, int w0, int e,
    const float* __restrict__ X,
    const float* __restrict__ W1, const float* __restrict__ W2,
    const float* __restrict__ W3,
    const float* __restrict__ B1, const float* __restrict__ B2c,
    const float* __restrict__ B3,
    float* __restrict__ den, float* __restrict__ outf)
{
    float* s_x  = sm + OFF_X;    // [3][38][38]
    float* s_c4 = sm + OFF_C4;   // [36][36]
    float* s_c5 = sm + OFF_C5;   // [34][34]
    float* s_w  = sm + OFF_W;    // 12 groups x 16
    float* s_b  = sm + OFF_B;
    float* s_M  = sm + OFF_M;
    float* s_B2 = sm + OFF_B2;

    // ---- weights (padded groups) + biases ----
    if (tid < 108) {
        const float* src;
        int grp, idx;
        if (tid < 27)      { src = W1; grp = tid / 9;             idx = tid % 9;        }
        else if (tid < 63) { src = W2; grp = 3 + (tid - 27) / 9;  idx = (tid - 27) % 9; }
        else               { src = W3; grp = 7 + (tid - 63) / 9;  idx = (tid - 63) % 9; }
        s_w[grp * 16 + idx] = __ldg(&src[grp < 3 ? tid : (grp < 7 ? tid - 27 : tid - 63)]);
    }
    if (tid == 120) s_b[0] = __ldg(&B1[0]);
    if (tid == 121) s_b[1] = __ldg(&B2c[0]);
    if (tid == 122) s_b[2] = __ldg(&B3[0]);

    // ---- input tile (3 ch, 38x38, 3-halo) ----
    #pragma unroll 1
    for (int c = 0; c < 3; c++) {
        const float* Xc = X + c * HWdim + (h0 - 3) * Wdim + (w0 - 3);
        #pragma unroll 1
        for (int idx = tid; idx < 38 * 38; idx += NT) {
            int r = idx / 38;
            int q = idx - r * 38;
            float v;
            if (INTERIOR) {
                v = __ldg(&Xc[r * Wdim + q]);
            } else {
                int gh = h0 - 3 + r, gw = w0 - 3 + q;
                v = 0.0f;
                if ((unsigned)gh < (unsigned)Hdim && (unsigned)gw < (unsigned)Wdim)
                    v = __ldg(&X[c * HWdim + gh * Wdim + gw]);
            }
            s_x[c * 1444 + idx] = v;
        }
    }
    __syncthreads();

    // ===== conv1: 3ch -> c4 (36x36), 2x2 blocked =====
    // Outside-image positions must be 0 (reference zero-pads the
    // concatenated tensor) -- only relevant for border blocks.
    {
        #pragma unroll 1
        for (int item = tid; item < 18 * 18; item += NT) {
            int jp = item / 18;
            int ip = item - jp * 18;
            int j = jp * 2, i = ip * 2;
            float a00 = 0, a01 = 0, a10 = 0, a11 = 0;
            ACC2X2_EVEN(s_x + 0 * 1444 + j * 38 + i, 38, s_w + 0);
            ACC2X2_EVEN(s_x + 1 * 1444 + j * 38 + i, 38, s_w + 16);
            ACC2X2_EVEN(s_x + 2 * 1444 + j * 38 + i, 38, s_w + 32);
            float bia = s_b[0];
            float2 r0, r1;
            if (INTERIOR) {
                r0 = make_float2(sigmoidf_(bia + a00), sigmoidf_(bia + a01));
                r1 = make_float2(sigmoidf_(bia + a10), sigmoidf_(bia + a11));
            } else {
                int gw = w0 + i - 2, gh = h0 + j - 2;
                bool wc0 = (unsigned)gw < (unsigned)Wdim;
                bool wc1 = (unsigned)(gw + 1) < (unsigned)Wdim;
                bool hc0 = (unsigned)gh < (unsigned)Hdim;
                bool hc1 = (unsigned)(gh + 1) < (unsigned)Hdim;
                r0 = make_float2(hc0 && wc0 ? sigmoidf_(bia + a00) : 0.0f,
                                 hc0 && wc1 ? sigmoidf_(bia + a01) : 0.0f);
                r1 = make_float2(hc1 && wc0 ? sigmoidf_(bia + a10) : 0.0f,
                                 hc1 && wc1 ? sigmoidf_(bia + a11) : 0.0f);
            }
            *(float2*)(s_c4 + j * 36 + i)       = r0;
            *(float2*)(s_c4 + (j + 1) * 36 + i) = r1;
        }
    }
    __syncthreads();

    // ===== conv2: [x,c4] -> c5 (34x34), 2x2 blocked =====
    {
        #pragma unroll 1
        for (int item = tid; item < 17 * 17; item += NT) {
            int jp = item / 17;
            int ip = item - jp * 17;
            int j = jp * 2, i = ip * 2;
            float a00 = 0, a01 = 0, a10 = 0, a11 = 0;
            ACC2X2_ODD (s_x + 0 * 1444 + (j + 1) * 38 + i, 38, s_w + 48);
            ACC2X2_ODD (s_x + 1 * 1444 + (j + 1) * 38 + i, 38, s_w + 64);
            ACC2X2_ODD (s_x + 2 * 1444 + (j + 1) * 38 + i, 38, s_w + 80);
            ACC2X2_EVEN(s_c4 + j * 36 + i,                  36, s_w + 96);
            float bia = s_b[1];
            float2 r0, r1;
            if (INTERIOR) {
                r0 = make_float2(sigmoidf_(bia + a00), sigmoidf_(bia + a01));
                r1 = make_float2(sigmoidf_(bia + a10), sigmoidf_(bia + a11));
            } else {
                int gw = w0 + i - 1, gh = h0 + j - 1;
                bool wc0 = (unsigned)gw < (unsigned)Wdim;
                bool wc1 = (unsigned)(gw + 1) < (unsigned)Wdim;
                bool hc0 = (unsigned)gh < (unsigned)Hdim;
                bool hc1 = (unsigned)(gh + 1) < (unsigned)Hdim;
                r0 = make_float2(hc0 && wc0 ? sigmoidf_(bia + a00) : 0.0f,
                                 hc0 && wc1 ? sigmoidf_(bia + a01) : 0.0f);
                r1 = make_float2(hc1 && wc0 ? sigmoidf_(bia + a10) : 0.0f,
                                 hc1 && wc1 ? sigmoidf_(bia + a11) : 0.0f);
            }
            *(float2*)(s_c5 + j * 34 + i)       = r0;
            *(float2*)(s_c5 + (j + 1) * 34 + i) = r1;
        }
    }
    __syncthreads();

    // ===== conv3: [x,c4,c5] -> c6 + den + outf (32x32), 2 quads/thread =====
    {
        const float4 M03  = *(const float4*)(s_M);
        const float4 M47  = *(const float4*)(s_M + 4);
        const float4 M811 = *(const float4*)(s_M + 8);
        const float2 Bv   = *(const float2*)(s_B2);

        #pragma unroll 1
        for (int k = 0; k < 2; k++) {
            int item = tid + k * NT;   // 256 items exactly (16x16 quads)
            int jp = item >> 4;
            int ip = item & 15;
            int j = jp * 2, i = ip * 2;
            float a00 = 0, a01 = 0, a10 = 0, a11 = 0;
            ACC2X2_EVEN(s_x + 0 * 1444 + (j + 2) * 38 + (i + 2), 38, s_w + 112);
            ACC2X2_EVEN(s_x + 1 * 1444 + (j + 2) * 38 + (i + 2), 38, s_w + 128);
            ACC2X2_EVEN(s_x + 2 * 1444 + (j + 2) * 38 + (i + 2), 38, s_w + 144);
            ACC2X2_ODD (s_c4 + (j + 1) * 36 + i,                  36, s_w + 160);
            ACC2X2_EVEN(s_c5 + j * 34 + i,                        34, s_w + 176);
            float bia = s_b[2];

            float accs[2][2] = {{a00, a01}, {a10, a11}};
            #pragma unroll
            for (int r = 0; r < 2; r++) {
                int jj = j + r;
                float fA5 = sigmoidf_(bia + accs[r][0]);
                float fB5 = sigmoidf_(bia + accs[r][1]);
                const float* xc = s_x + (jj + 3) * 38 + (i + 3);
                float fA0 = xc[0],    fB0 = xc[1];
                float fA1 = xc[1444], fB1 = xc[1445];
                float fA2 = xc[2888], fB2 = xc[2889];
                float fA3 = s_c4[(jj + 2) * 36 + (i + 2)];
                float fB3 = s_c4[(jj + 2) * 36 + (i + 3)];
                float fA4 = s_c5[(jj + 1) * 34 + (i + 1)];
                float fB4 = s_c5[(jj + 1) * 34 + (i + 2)];

                int pix = (h0 + jj) * Wdim + (w0 + i);   // even
                float4* dp = (float4*)(den + (size_t)pix * 6);
                dp[0] = make_float4(fA0, fA1, fA2, fA3);
                dp[1] = make_float4(fA4, fA5, fB0, fB1);
                dp[2] = make_float4(fB2, fB3, fB4, fB5);

                float mA0 = M03.x*fA0 + M03.y*fA1 + M03.z*fA2
                          + M03.w*fA3 + M47.x*fA4 + M47.y*fA5;
                float mA1 = M47.z*fA0 + M47.w*fA1 + M811.x*fA2
                          + M811.y*fA3 + M811.z*fA4 + M811.w*fA5;
                float mB0 = M03.x*fB0 + M03.y*fB1 + M03.z*fB2
                          + M03.w*fB3 + M47.x*fB4 + M47.y*fB5;
                float mB1 = M47.z*fB0 + M47.w*fB1 + M811.x*fB2
                          + M811.y*fB3 + M811.z*fB4 + M811.w*fB5;

                float4* op = (float4*)(outf + (size_t)pix * 2);
                if (e == 0) {
                    *op = make_float4(Bv.x + mA0, Bv.y + mA1,
                                      Bv.x + mB0, Bv.y + mB1);
                } else {
                    float4 prev = *op;  // same thread wrote it in e=0
                    *op = make_float4(prev.x - mA0, prev.y - mA1,
                                      prev.z - mB0, prev.w - mB1);
                }
            }
        }
    }
}

__global__ __launch_bounds__(NT, 8) void unet_fused_kernel(
    const float* __restrict__ x,  const float* __restrict__ x2,
    const float* __restrict__ w1a, const float* __restrict__ b1a,
    const float* __restrict__ w2a, const float* __restrict__ b2a,
    const float* __restrict__ w3a, const float* __restrict__ b3a,
    const float* __restrict__ w1b, const float* __restrict__ b1b,
    const float* __restrict__ w2b, const float* __restrict__ b2b,
    const float* __restrict__ w3b, const float* __restrict__ b3b,
    float* __restrict__ outf, float* __restrict__ den1, float* __restrict__ den2)
{
    extern __shared__ float sm[];
    const int tid = threadIdx.x;
    const int h0  = blockIdx.y * TSH;
    const int w0  = blockIdx.x * TSW;

    if (tid < 12) (sm + OFF_M)[tid] = g_M[tid];
    if (tid >= 12 && tid < 14) (sm + OFF_B2)[tid - 12] = g_B[tid - 12];

    const bool interior = (h0 >= 3) && (h0 + TSH + 3 <= Hdim)
                       && (w0 >= 3) && (w0 + TSW + 3 <= Wdim);

    if (interior) {
        #pragma unroll 1
        for (int e = 0; e < 2; e++) {
            __syncthreads();
            encoder_pass<true>(sm, tid, h0, w0, e,
                e ? x2 : x,
                e ? w1b : w1a, e ? w2b : w2a, e ? w3b : w3a,
                e ? b1b : b1a, e ? b2b : b2a, e ? b3b : b3a,
                e ? den2 : den1, outf);
        }
    } else {
        #pragma unroll 1
        for (int e = 0; e < 2; e++) {
            __syncthreads();
            encoder_pass<false>(sm, tid, h0, w0, e,
                e ? x2 : x,
                e ? w1b : w1a, e ? w2b : w2a, e ? w3b : w3a,
                e ? b1b : b1a, e ? b2b : b2a, e ? b3b : b3a,
                e ? den2 : den1, outf);
        }
    }
}

extern "C" void kernel_launch(void* const* d_in, const int* in_sizes, int n_in,
                              void* d_out, int out_size) {
    const float* x   = (const float*)d_in[0];
    const float* x2  = (const float*)d_in[1];
    const float* w1a = (const float*)d_in[2];
    const float* b1a = (const float*)d_in[3];
    const float* w2a = (const float*)d_in[4];
    const float* b2a = (const float*)d_in[5];
    const float* w3a = (const float*)d_in[6];
    const float* b3a = (const float*)d_in[7];
    const float* w1b = (const float*)d_in[8];
    const float* b1b = (const float*)d_in[9];
    const float* w2b = (const float*)d_in[10];
    const float* b2b = (const float*)d_in[11];
    const float* w3b = (const float*)d_in[12];
    const float* b3b = (const float*)d_in[13];
    const float* lw1 = (const float*)d_in[14];
    const float* lb1 = (const float*)d_in[15];
    const float* lw2 = (const float*)d_in[16];
    const float* lb2 = (const float*)d_in[17];

    float* outf = (float*)d_out;                       // [HW, 2]
    float* den1 = (float*)d_out + (size_t)2 * HWdim;   // [H, W, 6]
    float* den2 = (float*)d_out + (size_t)8 * HWdim;   // [H, W, 6]

    cudaFuncSetAttribute(unet_fused_kernel,
                         cudaFuncAttributeMaxDynamicSharedMemorySize, SMEM_BYTES);

    fold_mlp_kernel<<<1, 32>>>(lw1, lb1, lw2, lb2);

    dim3 grid(Wdim / TSW, Hdim / TSH);
    unet_fused_kernel<<<grid, NT, SMEM_BYTES>>>(
        x, x2, w1a, b1a, w2a, b2a, w3a, b3a,
        w1b, b1b, w2b, b2b, w3b, b3b,
        outf, den1, den2);
}

// round 17
// speedup vs baseline: 1.0370x; 1.0370x over previous
#include <cuda_runtime.h>

#define Hdim 1024
#define Wdim 1024
#define HWdim (Hdim * Wdim)
#define TSH 32
#define TSW 32
#define NT 128

// smem float offsets (OFF_W 16B-aligned; weight groups padded to 16 floats)
#define OFF_X   0            // [3][38][38]
#define OFF_C4  4332         // [36][36]
#define OFF_C5  5628         // [34][34]
#define OFF_W   6784         // 12 groups x 16 floats (9 used, padded)
#define OFF_B   6976         // [3]
#define OFF_M   6980         // [12]
#define OFF_B2  6992         // [2]
#define SMEM_FLOATS 6994
#define SMEM_BYTES (SMEM_FLOATS * 4)

__device__ float g_M[12];
__device__ float g_B[2];

__global__ void fold_mlp_kernel(const float* __restrict__ lw1,
                                const float* __restrict__ lb1,
                                const float* __restrict__ lw2,
                                const float* __restrict__ lb2) {
    int t = threadIdx.x;
    if (t < 12) {
        int o = t / 6, c = t % 6;
        float acc = 0.0f;
        #pragma unroll 8
        for (int k = 0; k < 128; k++)
            acc += lw2[o * 128 + k] * lw1[k * 6 + c];
        g_M[t] = acc;
    } else if (t < 14) {
        int o = t - 12;
        float acc = lb2[o];
        #pragma unroll 8
        for (int k = 0; k < 128; k++)
            acc += lw2[o * 128 + k] * lb1[k];
        g_B[o] = acc;
    }
}

__device__ __forceinline__ float sigmoidf_(float y) {
    return __fdividef(1.0f, 1.0f + __expf(-y));
}

// 2x2-output conv accumulate, window starts at P (8B-aligned).
// WSM: 16B-aligned 9-weight group -> 2x LDS.128 + 1x LDS.32 (broadcast).
// Live weight count unchanged vs scalar version (9 floats).
#define LOADW9(WSM, wc) do {                                                 \
    float4 _tA = *(const float4*)(WSM);                                      \
    float4 _tB = *(const float4*)((WSM) + 4);                                \
    wc[0] = _tA.x; wc[1] = _tA.y; wc[2] = _tA.z; wc[3] = _tA.w;              \
    wc[4] = _tB.x; wc[5] = _tB.y; wc[6] = _tB.z; wc[7] = _tB.w;              \
    wc[8] = (WSM)[8];                                                        \
} while (0)

#define ACC2X2_EVEN(P, S, WSM) do {                                          \
    float wc[9];                                                             \
    LOADW9(WSM, wc);                                                         \
    _Pragma("unroll")                                                        \
    for (int rr = 0; rr < 4; rr++) {                                         \
        float2 A = *(const float2*)((P) + rr * (S));                         \
        float2 B = *(const float2*)((P) + rr * (S) + 2);                     \
        if (rr <= 2) {                                                       \
            a00 += wc[rr*3+0]*A.x + wc[rr*3+1]*A.y + wc[rr*3+2]*B.x;         \
            a01 += wc[rr*3+0]*A.y + wc[rr*3+1]*B.x + wc[rr*3+2]*B.y;         \
        }                                                                    \
        if (rr >= 1) {                                                       \
            a10 += wc[(rr-1)*3+0]*A.x + wc[(rr-1)*3+1]*A.y + wc[(rr-1)*3+2]*B.x; \
            a11 += wc[(rr-1)*3+0]*A.y + wc[(rr-1)*3+1]*B.x + wc[(rr-1)*3+2]*B.y; \
        }                                                                    \
    }                                                                        \
} while (0)

// Same, but the logical window starts at P+1 (P 8B-aligned): 3x LDS.64 per row.
#define ACC2X2_ODD(P, S, WSM) do {                                           \
    float wc[9];                                                             \
    LOADW9(WSM, wc);                                                         \
    _Pragma("unroll")                                                        \
    for (int rr = 0; rr < 4; rr++) {                                         \
        float2 A = *(const float2*)((P) + rr * (S));                         \
        float2 B = *(const float2*)((P) + rr * (S) + 2);                     \
        float2 C = *(const float2*)((P) + rr * (S) + 4);                     \
        if (rr <= 2) {                                                       \
            a00 += wc[rr*3+0]*A.y + wc[rr*3+1]*B.x + wc[rr*3+2]*B.y;         \
            a01 += wc[rr*3+0]*B.x + wc[rr*3+1]*B.y + wc[rr*3+2]*C.x;         \
        }                                                                    \
        if (rr >= 1) {                                                       \
            a10 += wc[(rr-1)*3+0]*A.y + wc[(rr-1)*3+1]*B.x + wc[(rr-1)*3+2]*B.y; \
            a11 += wc[(rr-1)*3+0]*B.x + wc[(rr-1)*3+1]*B.y + wc[(rr-1)*3+2]*C.x; \
        }                                                                    \
    }                                                                        \
} while (0)

template <bool INTERIOR>
__device__ __forceinline__ void encoder_pass(
    float* __restrict__ sm, int tid, int h0, int w0, int e,
    const float* __restrict__ X,
    const float* __restrict__ W1, const float* __restrict__ W2,
    const float* __restrict__ W3,
    const float* __restrict__ B1, const float* __restrict__ B2c,
    const float* __restrict__ B3,
    float* __restrict__ den, float* __restrict__ outf)
{
    float* s_x  = sm + OFF_X;    // [3][38][38]
    float* s_c4 = sm + OFF_C4;   // [36][36]
    float* s_c5 = sm + OFF_C5;   // [34][34]
    float* s_w  = sm + OFF_W;    // 12 groups x 16
    float* s_b  = sm + OFF_B;
    float* s_M  = sm + OFF_M;
    float* s_B2 = sm + OFF_B2;

    // ---- weights (padded 16-float groups) + biases ----
    if (tid < 108) {
        const float* src;
        int off, grp, idx;
        if (tid < 27)      { src = W1; off = tid;      grp = tid / 9;            }
        else if (tid < 63) { src = W2; off = tid - 27; grp = 3 + (tid - 27) / 9; }
        else               { src = W3; off = tid - 63; grp = 7 + (tid - 63) / 9; }
        idx = off % 9;
        s_w[grp * 16 + idx] = __ldg(&src[off]);
    }
    if (tid == 120) s_b[0] = __ldg(&B1[0]);
    if (tid == 121) s_b[1] = __ldg(&B2c[0]);
    if (tid == 122) s_b[2] = __ldg(&B3[0]);

    // ---- input tile (3 ch, 38x38, 3-halo) ----
    #pragma unroll 1
    for (int c = 0; c < 3; c++) {
        const float* Xc = X + c * HWdim + (h0 - 3) * Wdim + (w0 - 3);
        #pragma unroll 1
        for (int idx = tid; idx < 38 * 38; idx += NT) {
            int r = idx / 38;
            int q = idx - r * 38;
            float v;
            if (INTERIOR) {
                v = __ldg(&Xc[r * Wdim + q]);
            } else {
                int gh = h0 - 3 + r, gw = w0 - 3 + q;
                v = 0.0f;
                if ((unsigned)gh < (unsigned)Hdim && (unsigned)gw < (unsigned)Wdim)
                    v = __ldg(&X[c * HWdim + gh * Wdim + gw]);
            }
            s_x[c * 1444 + idx] = v;
        }
    }
    __syncthreads();

    // ===== conv1: 3ch -> c4 (36x36), 2x2 blocked =====
    // Outside-image positions must be 0 (reference zero-pads the
    // concatenated tensor) -- only relevant for border blocks.
    {
        #pragma unroll 1
        for (int item = tid; item < 18 * 18; item += NT) {
            int jp = item / 18;
            int ip = item - jp * 18;
            int j = jp * 2, i = ip * 2;
            float a00 = 0, a01 = 0, a10 = 0, a11 = 0;
            ACC2X2_EVEN(s_x + 0 * 1444 + j * 38 + i, 38, s_w + 0);
            ACC2X2_EVEN(s_x + 1 * 1444 + j * 38 + i, 38, s_w + 16);
            ACC2X2_EVEN(s_x + 2 * 1444 + j * 38 + i, 38, s_w + 32);
            float bia = s_b[0];
            float2 r0, r1;
            if (INTERIOR) {
                r0 = make_float2(sigmoidf_(bia + a00), sigmoidf_(bia + a01));
                r1 = make_float2(sigmoidf_(bia + a10), sigmoidf_(bia + a11));
            } else {
                int gw = w0 + i - 2, gh = h0 + j - 2;
                bool wc0 = (unsigned)gw < (unsigned)Wdim;
                bool wc1 = (unsigned)(gw + 1) < (unsigned)Wdim;
                bool hc0 = (unsigned)gh < (unsigned)Hdim;
                bool hc1 = (unsigned)(gh + 1) < (unsigned)Hdim;
                r0 = make_float2(hc0 && wc0 ? sigmoidf_(bia + a00) : 0.0f,
                                 hc0 && wc1 ? sigmoidf_(bia + a01) : 0.0f);
                r1 = make_float2(hc1 && wc0 ? sigmoidf_(bia + a10) : 0.0f,
                                 hc1 && wc1 ? sigmoidf_(bia + a11) : 0.0f);
            }
            *(float2*)(s_c4 + j * 36 + i)       = r0;
            *(float2*)(s_c4 + (j + 1) * 36 + i) = r1;
        }
    }
    __syncthreads();

    // ===== conv2: [x,c4] -> c5 (34x34), 2x2 blocked =====
    {
        #pragma unroll 1
        for (int item = tid; item < 17 * 17; item += NT) {
            int jp = item / 17;
            int ip = item - jp * 17;
            int j = jp * 2, i = ip * 2;
            float a00 = 0, a01 = 0, a10 = 0, a11 = 0;
            ACC2X2_ODD (s_x + 0 * 1444 + (j + 1) * 38 + i, 38, s_w + 48);
            ACC2X2_ODD (s_x + 1 * 1444 + (j + 1) * 38 + i, 38, s_w + 64);
            ACC2X2_ODD (s_x + 2 * 1444 + (j + 1) * 38 + i, 38, s_w + 80);
            ACC2X2_EVEN(s_c4 + j * 36 + i,                  36, s_w + 96);
            float bia = s_b[1];
            float2 r0, r1;
            if (INTERIOR) {
                r0 = make_float2(sigmoidf_(bia + a00), sigmoidf_(bia + a01));
                r1 = make_float2(sigmoidf_(bia + a10), sigmoidf_(bia + a11));
            } else {
                int gw = w0 + i - 1, gh = h0 + j - 1;
                bool wc0 = (unsigned)gw < (unsigned)Wdim;
                bool wc1 = (unsigned)(gw + 1) < (unsigned)Wdim;
                bool hc0 = (unsigned)gh < (unsigned)Hdim;
                bool hc1 = (unsigned)(gh + 1) < (unsigned)Hdim;
                r0 = make_float2(hc0 && wc0 ? sigmoidf_(bia + a00) : 0.0f,
                                 hc0 && wc1 ? sigmoidf_(bia + a01) : 0.0f);
                r1 = make_float2(hc1 && wc0 ? sigmoidf_(bia + a10) : 0.0f,
                                 hc1 && wc1 ? sigmoidf_(bia + a11) : 0.0f);
            }
            *(float2*)(s_c5 + j * 34 + i)       = r0;
            *(float2*)(s_c5 + (j + 1) * 34 + i) = r1;
        }
    }
    __syncthreads();

    // ===== conv3: [x,c4,c5] -> c6 + den + outf (32x32), 2 quads/thread =====
    {
        #pragma unroll 1
        for (int k = 0; k < 2; k++) {
            int item = tid + k * NT;   // 256 items exactly (16x16 quads)
            int jp = item >> 4;
            int ip = item & 15;
            int j = jp * 2, i = ip * 2;
            float a00 = 0, a01 = 0, a10 = 0, a11 = 0;
            ACC2X2_EVEN(s_x + 0 * 1444 + (j + 2) * 38 + (i + 2), 38, s_w + 112);
            ACC2X2_EVEN(s_x + 1 * 1444 + (j + 2) * 38 + (i + 2), 38, s_w + 128);
            ACC2X2_EVEN(s_x + 2 * 1444 + (j + 2) * 38 + (i + 2), 38, s_w + 144);
            ACC2X2_ODD (s_c4 + (j + 1) * 36 + i,                  36, s_w + 160);
            ACC2X2_EVEN(s_c5 + j * 34 + i,                        34, s_w + 176);
            float bia = s_b[2];

            float accs[2][2] = {{a00, a01}, {a10, a11}};
            #pragma unroll
            for (int r = 0; r < 2; r++) {
                int jj = j + r;
                float fA5 = sigmoidf_(bia + accs[r][0]);
                float fB5 = sigmoidf_(bia + accs[r][1]);
                const float* xc = s_x + (jj + 3) * 38 + (i + 3);
                float fA0 = xc[0],    fB0 = xc[1];
                float fA1 = xc[1444], fB1 = xc[1445];
                float fA2 = xc[2888], fB2 = xc[2889];
                float fA3 = s_c4[(jj + 2) * 36 + (i + 2)];
                float fB3 = s_c4[(jj + 2) * 36 + (i + 3)];
                float fA4 = s_c5[(jj + 1) * 34 + (i + 1)];
                float fB4 = s_c5[(jj + 1) * 34 + (i + 2)];

                int pix = (h0 + jj) * Wdim + (w0 + i);   // even
                float4* dp = (float4*)(den + (size_t)pix * 6);
                dp[0] = make_float4(fA0, fA1, fA2, fA3);
                dp[1] = make_float4(fA4, fA5, fB0, fB1);
                dp[2] = make_float4(fB2, fB3, fB4, fB5);

                float mA0 = s_M[0]*fA0 + s_M[1]*fA1 + s_M[2]*fA2
                          + s_M[3]*fA3 + s_M[4]*fA4 + s_M[5]*fA5;
                float mA1 = s_M[6]*fA0 + s_M[7]*fA1 + s_M[8]*fA2
                          + s_M[9]*fA3 + s_M[10]*fA4 + s_M[11]*fA5;
                float mB0 = s_M[0]*fB0 + s_M[1]*fB1 + s_M[2]*fB2
                          + s_M[3]*fB3 + s_M[4]*fB4 + s_M[5]*fB5;
                float mB1 = s_M[6]*fB0 + s_M[7]*fB1 + s_M[8]*fB2
                          + s_M[9]*fB3 + s_M[10]*fB4 + s_M[11]*fB5;

                float4* op = (float4*)(outf + (size_t)pix * 2);
                if (e == 0) {
                    *op = make_float4(s_B2[0] + mA0, s_B2[1] + mA1,
                                      s_B2[0] + mB0, s_B2[1] + mB1);
                } else {
                    float4 prev = *op;  // same thread wrote it in e=0
                    *op = make_float4(prev.x - mA0, prev.y - mA1,
                                      prev.z - mB0, prev.w - mB1);
                }
            }
        }
    }
}

__global__ __launch_bounds__(NT, 8) void unet_fused_kernel(
    const float* __restrict__ x,  const float* __restrict__ x2,
    const float* __restrict__ w1a, const float* __restrict__ b1a,
    const float* __restrict__ w2a, const float* __restrict__ b2a,
    const float* __restrict__ w3a, const float* __restrict__ b3a,
    const float* __restrict__ w1b, const float* __restrict__ b1b,
    const float* __restrict__ w2b, const float* __restrict__ b2b,
    const float* __restrict__ w3b, const float* __restrict__ b3b,
    float* __restrict__ outf, float* __restrict__ den1, float* __restrict__ den2)
{
    extern __shared__ float sm[];
    const int tid = threadIdx.x;
    const int h0  = blockIdx.y * TSH;
    const int w0  = blockIdx.x * TSW;

    if (tid < 12) (sm + OFF_M)[tid] = g_M[tid];
    if (tid >= 12 && tid < 14) (sm + OFF_B2)[tid - 12] = g_B[tid - 12];

    const bool interior = (h0 >= 3) && (h0 + TSH + 3 <= Hdim)
                       && (w0 >= 3) && (w0 + TSW + 3 <= Wdim);

    if (interior) {
        #pragma unroll 1
        for (int e = 0; e < 2; e++) {
            __syncthreads();
            encoder_pass<true>(sm, tid, h0, w0, e,
                e ? x2 : x,
                e ? w1b : w1a, e ? w2b : w2a, e ? w3b : w3a,
                e ? b1b : b1a, e ? b2b : b2a, e ? b3b : b3a,
                e ? den2 : den1, outf);
        }
    } else {
        #pragma unroll 1
        for (int e = 0; e < 2; e++) {
            __syncthreads();
            encoder_pass<false>(sm, tid, h0, w0, e,
                e ? x2 : x,
                e ? w1b : w1a, e ? w2b : w2a, e ? w3b : w3a,
                e ? b1b : b1a, e ? b2b : b2a, e ? b3b : b3a,
                e ? den2 : den1, outf);
        }
    }
}

extern "C" void kernel_launch(void* const* d_in, const int* in_sizes, int n_in,
                              void* d_out, int out_size) {
    const float* x   = (const float*)d_in[0];
    const float* x2  = (const float*)d_in[1];
    const float* w1a = (const float*)d_in[2];
    const float* b1a = (const float*)d_in[3];
    const float* w2a = (const float*)d_in[4];
    const float* b2a = (const float*)d_in[5];
    const float* w3a = (const float*)d_in[6];
    const float* b3a = (const float*)d_in[7];
    const float* w1b = (const float*)d_in[8];
    const float* b1b = (const float*)d_in[9];
    const float* w2b = (const float*)d_in[10];
    const float* b2b = (const float*)d_in[11];
    const float* w3b = (const float*)d_in[12];
    const float* b3b = (const float*)d_in[13];
    const float* lw1 = (const float*)d_in[14];
    const float* lb1 = (const float*)d_in[15];
    const float* lw2 = (const float*)d_in[16];
    const float* lb2 = (const float*)d_in[17];

    float* outf = (float*)d_out;                       // [HW, 2]
    float* den1 = (float*)d_out + (size_t)2 * HWdim;   // [H, W, 6]
    float* den2 = (float*)d_out + (size_t)8 * HWdim;   // [H, W, 6]

    cudaFuncSetAttribute(unet_fused_kernel,
                         cudaFuncAttributeMaxDynamicSharedMemorySize, SMEM_BYTES);

    fold_mlp_kernel<<<1, 32>>>(lw1, lb1, lw2, lb2);

    dim3 grid(Wdim / TSW, Hdim / TSH);
    unet_fused_kernel<<<grid, NT, SMEM_BYTES>>>(
        x, x2, w1a, b1a, w2a, b2a, w3a, b3a,
        w1b, b1b, w2b, b2b, w3b, b3b,
        outf, den1, den2);
}